// round 8
// baseline (speedup 1.0000x reference)
#include <cuda_runtime.h>
#include <cuda_fp16.h>
#include <mma.h>
#include <cfloat>

using namespace nvcuda;

#define NN   50000
#define EE   800000
#define ECAP 64        // ELL capacity for real edges (Poisson(16); P(deg>63) ~ 1e-18)
#define NEG_SLOPE 0.2f
#define BN_EPS 1e-5f
#define LDA 136

// ---------------- scratch (device globals) ----------------
__device__ int g_cnt[NN];
__device__ __align__(16) int g_ell[(size_t)NN * ECAP];
__device__ __align__(16) __half g_h1h [NN * 128];
__device__ float g_al1s[NN * 2];
__device__ float g_al1d[NN * 2];
__device__ __align__(16) __half g_out1h[NN * 128];
__device__ __align__(16) __half g_h2h [NN * 40];
__device__ float g_al2s[NN];
__device__ float g_al2d[NN];

// ---------------- helpers ----------------
__device__ __forceinline__ float lrelu(float x) { return x > 0.f ? x : NEG_SLOPE * x; }
__device__ __forceinline__ float warpSum(float v) {
    #pragma unroll
    for (int o = 16; o; o >>= 1) v += __shfl_xor_sync(0xffffffffu, v, o);
    return v;
}
__device__ __forceinline__ float warpMax(float v) {
    #pragma unroll
    for (int o = 16; o; o >>= 1) v = fmaxf(v, __shfl_xor_sync(0xffffffffu, v, o));
    return v;
}

// ================= K1: scatter edges into ELL (cnt pre-zeroed by memset) =================
__global__ void k_scatter(const int* __restrict__ ei) {
    int t = blockIdx.x * blockDim.x + threadIdx.x;
    if (t >= EE / 4) return;
    int4 s4 = *(const int4*)(ei + t * 4);
    int4 d4 = *(const int4*)(ei + EE + t * 4);
    int p;
    p = atomicAdd(&g_cnt[d4.x], 1); g_ell[(size_t)d4.x * ECAP + p] = s4.x;
    p = atomicAdd(&g_cnt[d4.y], 1); g_ell[(size_t)d4.y * ECAP + p] = s4.y;
    p = atomicAdd(&g_cnt[d4.z], 1); g_ell[(size_t)d4.z * ECAP + p] = s4.z;
    p = atomicAdd(&g_cnt[d4.w], 1); g_ell[(size_t)d4.w * ECAP + p] = s4.w;
}

// ================= K2: GEMM1 wmma fp16, 64-row tiles =================
__global__ __launch_bounds__(256) void k_gemm1(const float* __restrict__ X,
                                               const float* __restrict__ W,
                                               const float* __restrict__ a1s,
                                               const float* __restrict__ a1d) {
    extern __shared__ __align__(16) __half dyn[];
    __half* sA = dyn;                  // 64 x LDA
    __half* sW = dyn + 64 * LDA;       // 128 x LDA
    __shared__ float sAs[128], sAd[128];

    const int tid = threadIdx.x;
    const int warp = tid >> 5, lane = tid & 31;
    const int row0 = blockIdx.x * 64;
    const int validRows = min(64, NN - row0);

    if (tid < 128) { sAs[tid] = a1s[tid]; sAd[tid] = a1d[tid]; }

    #pragma unroll
    for (int i = 0; i < 8; i++) {
        int idx = tid + i * 256;
        int r = idx >> 5, c = (idx & 31) * 4;
        float4 v = make_float4(0.f, 0.f, 0.f, 0.f);
        if (r < validRows) v = *(const float4*)(X + (size_t)(row0 + r) * 128 + c);
        __half2 h0 = __floats2half2_rn(v.x, v.y);
        __half2 h1 = __floats2half2_rn(v.z, v.w);
        uint2 st; st.x = *(unsigned*)&h0; st.y = *(unsigned*)&h1;
        *(uint2*)(sA + r * LDA + c) = st;
    }
    #pragma unroll
    for (int i = 0; i < 16; i++) {
        int idx = tid + i * 256;
        int r = idx >> 5, c = (idx & 31) * 4;
        float4 v = *(const float4*)(W + (size_t)r * 128 + c);
        __half2 h0 = __floats2half2_rn(v.x, v.y);
        __half2 h1 = __floats2half2_rn(v.z, v.w);
        uint2 st; st.x = *(unsigned*)&h0; st.y = *(unsigned*)&h1;
        *(uint2*)(sW + r * LDA + c) = st;
    }
    __syncthreads();

    const int wr = warp & 3;
    const int wc = warp >> 2;

    wmma::fragment<wmma::accumulator, 16, 16, 16, float> acc[4];
    #pragma unroll
    for (int nf = 0; nf < 4; nf++) wmma::fill_fragment(acc[nf], 0.f);
    #pragma unroll
    for (int k0 = 0; k0 < 128; k0 += 16) {
        wmma::fragment<wmma::matrix_a, 16, 16, 16, __half, wmma::row_major> af;
        wmma::load_matrix_sync(af, sA + (wr * 16) * LDA + k0, LDA);
        #pragma unroll
        for (int nf = 0; nf < 4; nf++) {
            wmma::fragment<wmma::matrix_b, 16, 16, 16, __half, wmma::row_major> bf;
            wmma::load_matrix_sync(bf, sW + k0 * LDA + wc * 64 + nf * 16, LDA);
            wmma::mma_sync(acc[nf], af, bf, acc[nf]);
        }
    }
    __syncthreads();

    float* sC = (float*)dyn + warp * 320;
    const int rloc = lane & 15;
    const int coff = (lane >> 4) * 8;
    const int gr = row0 + wr * 16 + rloc;
    float ps = 0.f, pd = 0.f;

    #pragma unroll
    for (int nf = 0; nf < 4; nf++) {
        wmma::store_matrix_sync(sC, acc[nf], 20, wmma::mem_row_major);
        __syncwarp();
        float v[8];
        #pragma unroll
        for (int j = 0; j < 8; j++) v[j] = sC[rloc * 20 + coff + j];
        int cbase = wc * 64 + nf * 16 + coff;
        #pragma unroll
        for (int j = 0; j < 8; j++) { ps += v[j] * sAs[cbase + j]; pd += v[j] * sAd[cbase + j]; }
        if (gr < NN) {
            __half2 h0 = __floats2half2_rn(v[0], v[1]);
            __half2 h1 = __floats2half2_rn(v[2], v[3]);
            __half2 h2 = __floats2half2_rn(v[4], v[5]);
            __half2 h3 = __floats2half2_rn(v[6], v[7]);
            uint4 st;
            st.x = *(unsigned*)&h0; st.y = *(unsigned*)&h1;
            st.z = *(unsigned*)&h2; st.w = *(unsigned*)&h3;
            *(uint4*)(g_h1h + (size_t)gr * 128 + cbase) = st;
        }
        __syncwarp();
    }
    ps += __shfl_xor_sync(0xffffffffu, ps, 16);
    pd += __shfl_xor_sync(0xffffffffu, pd, 16);
    if (lane < 16 && gr < NN) {
        g_al1s[2 * gr + wc] = ps;
        g_al1d[2 * gr + wc] = pd;
    }
}

// ================= K3: layer-1 gather — 4 edges/step, 8 lanes/edge (MLP=8) =================
__global__ __launch_bounds__(256) void k_agg1(const float* __restrict__ b1,
                                              const float* __restrict__ gamma,
                                              const float* __restrict__ beta,
                                              const float* __restrict__ mean,
                                              const float* __restrict__ var) {
    int d = (blockIdx.x * blockDim.x + threadIdx.x) >> 5;
    int lane = threadIdx.x & 31;
    if (d >= NN) return;
    const int deg = g_cnt[d];                 // real edges only; self-loop analytic
    const int* row = g_ell + (size_t)d * ECAP;
    float2 ad = *(const float2*)(g_al1d + 2 * d);
    const int eg = lane >> 3;     // edge subgroup 0..3
    const int cg = lane & 7;      // column group: cols cg*16 .. cg*16+15
    const bool head1 = (cg >= 4);

    // self-loop term
    float2 asd = *(const float2*)(g_al1s + 2 * d);
    float e0s = __expf(lrelu(asd.x + ad.x));
    float e1s = __expf(lrelu(asd.y + ad.y));
    float s0 = (lane == 0) ? e0s : 0.f;
    float s1 = (lane == 0) ? e1s : 0.f;

    float facc[16];
    #pragma unroll
    for (int k = 0; k < 16; k++) facc[k] = 0.f;
    if (eg == 0) {
        float ws = head1 ? e1s : e0s;
        const __half* hp = g_h1h + (size_t)d * 128 + cg * 16;
        uint4 r0 = *(const uint4*)hp;
        uint4 r1 = *(const uint4*)(hp + 8);
        float2 f;
        f = __half22float2(*(__half2*)&r0.x); facc[0]  = f.x * ws; facc[1]  = f.y * ws;
        f = __half22float2(*(__half2*)&r0.y); facc[2]  = f.x * ws; facc[3]  = f.y * ws;
        f = __half22float2(*(__half2*)&r0.z); facc[4]  = f.x * ws; facc[5]  = f.y * ws;
        f = __half22float2(*(__half2*)&r0.w); facc[6]  = f.x * ws; facc[7]  = f.y * ws;
        f = __half22float2(*(__half2*)&r1.x); facc[8]  = f.x * ws; facc[9]  = f.y * ws;
        f = __half22float2(*(__half2*)&r1.y); facc[10] = f.x * ws; facc[11] = f.y * ws;
        f = __half22float2(*(__half2*)&r1.z); facc[12] = f.x * ws; facc[13] = f.y * ws;
        f = __half22float2(*(__half2*)&r1.w); facc[14] = f.x * ws; facc[15] = f.y * ws;
    }

    for (int base = 0; base < deg; base += 32) {
        int i = base + lane;
        int src = 0; unsigned w01 = 0;     // zero weight for invalid slots
        if (i < deg) {
            src = row[i];
            float2 as = *(const float2*)(g_al1s + 2 * src);
            float e0 = __expf(lrelu(as.x + ad.x));
            float e1 = __expf(lrelu(as.y + ad.y));
            s0 += e0; s1 += e1;
            __half2 p = __floats2half2_rn(e0, e1);
            w01 = *(unsigned*)&p;
        }
        int cnt = min(32, deg - base);
        int steps = (cnt + 3) >> 2;

        __half2 hacc[8];
        #pragma unroll
        for (int k = 0; k < 8; k++) hacc[k] = __floats2half2_rn(0.f, 0.f);

        for (int j = 0; j < steps; j++) {
            int esel = 4 * j + eg;                       // 0..31
            int      sj = __shfl_sync(0xffffffffu, src, esel);
            unsigned wj = __shfl_sync(0xffffffffu, w01, esel);
            __half2 hw = head1 ? __high2half2(*(__half2*)&wj) : __low2half2(*(__half2*)&wj);
            const __half* hp = g_h1h + (size_t)sj * 128 + cg * 16;
            uint4 r0 = *(const uint4*)hp;
            uint4 r1 = *(const uint4*)(hp + 8);
            hacc[0] = __hfma2(*(__half2*)&r0.x, hw, hacc[0]);
            hacc[1] = __hfma2(*(__half2*)&r0.y, hw, hacc[1]);
            hacc[2] = __hfma2(*(__half2*)&r0.z, hw, hacc[2]);
            hacc[3] = __hfma2(*(__half2*)&r0.w, hw, hacc[3]);
            hacc[4] = __hfma2(*(__half2*)&r1.x, hw, hacc[4]);
            hacc[5] = __hfma2(*(__half2*)&r1.y, hw, hacc[5]);
            hacc[6] = __hfma2(*(__half2*)&r1.z, hw, hacc[6]);
            hacc[7] = __hfma2(*(__half2*)&r1.w, hw, hacc[7]);
        }
        #pragma unroll
        for (int k = 0; k < 8; k++) {
            float2 f = __half22float2(hacc[k]);
            facc[2 * k]     += f.x;
            facc[2 * k + 1] += f.y;
        }
    }
    // reduce across the 4 edge subgroups (same columns live at lane ^8, ^16)
    #pragma unroll
    for (int k = 0; k < 16; k++) {
        facc[k] += __shfl_xor_sync(0xffffffffu, facc[k], 8);
        facc[k] += __shfl_xor_sync(0xffffffffu, facc[k], 16);
    }
    s0 = warpSum(s0); s1 = warpSum(s1);

    if (lane < 8) {
        float inv = 1.f / ((head1 ? s1 : s0) + 1e-16f);
        int c0 = cg * 16;
        __half ho[16];
        #pragma unroll
        for (int q = 0; q < 4; q++) {
            int c = c0 + q * 4;
            float4 bv = *(const float4*)(b1 + c);
            float4 gm = *(const float4*)(gamma + c);
            float4 bt = *(const float4*)(beta + c);
            float4 mn = *(const float4*)(mean + c);
            float4 vr = *(const float4*)(var + c);
            ho[q*4+0] = __float2half(fmaxf((facc[q*4+0] * inv + bv.x - mn.x) * rsqrtf(vr.x + BN_EPS) * gm.x + bt.x, 0.f));
            ho[q*4+1] = __float2half(fmaxf((facc[q*4+1] * inv + bv.y - mn.y) * rsqrtf(vr.y + BN_EPS) * gm.y + bt.y, 0.f));
            ho[q*4+2] = __float2half(fmaxf((facc[q*4+2] * inv + bv.z - mn.z) * rsqrtf(vr.z + BN_EPS) * gm.z + bt.z, 0.f));
            ho[q*4+3] = __float2half(fmaxf((facc[q*4+3] * inv + bv.w - mn.w) * rsqrtf(vr.w + BN_EPS) * gm.w + bt.w, 0.f));
        }
        uint4* dst = (uint4*)(g_out1h + (size_t)d * 128 + c0);
        dst[0] = *(uint4*)&ho[0];
        dst[1] = *(uint4*)&ho[8];
    }
}

// ================= K4: GEMM2 wmma fp16 (out1@W2, N padded 40->48) =================
__global__ __launch_bounds__(256) void k_gemm2(const float* __restrict__ W2,
                                               const float* __restrict__ a2s,
                                               const float* __restrict__ a2d) {
    __shared__ __align__(16) __half sA[128 * 128];
    __shared__ __align__(16) __half sB[128 * 48];
    __shared__ float sAs[48], sAd[48];

    const int tid = threadIdx.x;
    const int warp = tid >> 5, lane = tid & 31;
    const int row0 = blockIdx.x * 128;

    if (tid < 48) {
        sAs[tid] = (tid < 40) ? a2s[tid] : 0.f;
        sAd[tid] = (tid < 40) ? a2d[tid] : 0.f;
    }
    for (int idx = tid; idx < 128 * 48; idx += 256) {
        int r = idx / 48, c = idx % 48;
        sB[idx] = __float2half(c < 40 ? W2[r * 40 + c] : 0.f);
    }
    {
        const int validRows = min(128, NN - row0);
        #pragma unroll
        for (int i = 0; i < 8; i++) {
            int v4 = tid + i * 256;
            int r = v4 >> 4;
            uint4 val = make_uint4(0, 0, 0, 0);
            if (r < validRows)
                val = *(const uint4*)(g_out1h + (size_t)(row0 + r) * 128 + (v4 & 15) * 8);
            *(uint4*)(sA + v4 * 8) = val;
        }
    }
    __syncthreads();

    wmma::fragment<wmma::accumulator, 16, 16, 16, float> acc[3];
    #pragma unroll
    for (int nf = 0; nf < 3; nf++) wmma::fill_fragment(acc[nf], 0.f);
    #pragma unroll
    for (int k0 = 0; k0 < 128; k0 += 16) {
        wmma::fragment<wmma::matrix_a, 16, 16, 16, __half, wmma::row_major> af;
        wmma::load_matrix_sync(af, sA + (warp * 16) * 128 + k0, 128);
        #pragma unroll
        for (int nf = 0; nf < 3; nf++) {
            wmma::fragment<wmma::matrix_b, 16, 16, 16, __half, wmma::row_major> bf;
            wmma::load_matrix_sync(bf, sB + k0 * 48 + nf * 16, 48);
            wmma::mma_sync(acc[nf], af, bf, acc[nf]);
        }
    }
    __syncthreads();

    float* sC = (float*)sA + warp * 320;
    const int rloc = lane & 15;
    const int coff = (lane >> 4) * 8;
    const int gr = row0 + warp * 16 + rloc;
    float ps = 0.f, pd = 0.f;

    #pragma unroll
    for (int nf = 0; nf < 3; nf++) {
        wmma::store_matrix_sync(sC, acc[nf], 20, wmma::mem_row_major);
        __syncwarp();
        float v[8];
        #pragma unroll
        for (int j = 0; j < 8; j++) v[j] = sC[rloc * 20 + coff + j];
        int cbase = nf * 16 + coff;
        #pragma unroll
        for (int j = 0; j < 8; j++) { ps += v[j] * sAs[cbase + j]; pd += v[j] * sAd[cbase + j]; }
        if (gr < NN && cbase < 40) {
            __half2 h0 = __floats2half2_rn(v[0], v[1]);
            __half2 h1 = __floats2half2_rn(v[2], v[3]);
            __half2 h2 = __floats2half2_rn(v[4], v[5]);
            __half2 h3 = __floats2half2_rn(v[6], v[7]);
            uint4 st;
            st.x = *(unsigned*)&h0; st.y = *(unsigned*)&h1;
            st.z = *(unsigned*)&h2; st.w = *(unsigned*)&h3;
            *(uint4*)(g_h2h + (size_t)gr * 40 + cbase) = st;
        }
        __syncwarp();
    }
    ps += __shfl_xor_sync(0xffffffffu, ps, 16);
    pd += __shfl_xor_sync(0xffffffffu, pd, 16);
    if (lane < 16 && gr < NN) { g_al2s[gr] = ps; g_al2d[gr] = pd; }
}

// ================= K5: layer-2 gather + analytic self-loop + log_softmax =================
__global__ __launch_bounds__(256) void k_agg2(float* __restrict__ dout,
                                              const float* __restrict__ b2) {
    int d = (blockIdx.x * blockDim.x + threadIdx.x) >> 5;
    int lane = threadIdx.x & 31;
    if (d >= NN) return;
    const int deg = g_cnt[d];
    const int* row = g_ell + (size_t)d * ECAP;
    float ad = g_al2d[d];
    const int half16 = lane >> 4;
    const int l16 = lane & 15;

    // self-loop
    float evs = __expf(lrelu(g_al2s[d] + ad));
    float ssum = (lane == 0) ? evs : 0.f;
    float facc[4];
    #pragma unroll
    for (int k = 0; k < 4; k++) facc[k] = 0.f;
    if (half16 == 0 && l16 < 10) {
        uint2 r = *(const uint2*)(g_h2h + (size_t)d * 40 + l16 * 4);
        float2 f0 = __half22float2(*(__half2*)&r.x);
        float2 f1 = __half22float2(*(__half2*)&r.y);
        facc[0] = f0.x * evs; facc[1] = f0.y * evs;
        facc[2] = f1.x * evs; facc[3] = f1.y * evs;
    }

    for (int base = 0; base < deg; base += 32) {
        int i = base + lane;
        int src = 0; float ev = 0.f;       // zero weight for invalid slots
        if (i < deg) {
            src = row[i];
            ev = __expf(lrelu(g_al2s[src] + ad));
            ssum += ev;
        }
        int cnt = min(32, deg - base);
        int pairs = (cnt + 1) >> 1;

        __half2 hacc[2];
        hacc[0] = hacc[1] = __floats2half2_rn(0.f, 0.f);
        for (int j = 0; j < pairs; j++) {
            int esel = 2 * j + half16;
            int   sj = __shfl_sync(0xffffffffu, src, esel);
            float ej = __shfl_sync(0xffffffffu, ev, esel);
            if (l16 < 10) {
                __half2 hw = __float2half2_rn(ej);
                uint2 r = *(const uint2*)(g_h2h + (size_t)sj * 40 + l16 * 4);
                hacc[0] = __hfma2(*(__half2*)&r.x, hw, hacc[0]);
                hacc[1] = __hfma2(*(__half2*)&r.y, hw, hacc[1]);
            }
        }
        float2 fa = __half22float2(hacc[0]);
        float2 fb = __half22float2(hacc[1]);
        facc[0] += fa.x; facc[1] += fa.y;
        facc[2] += fb.x; facc[3] += fb.y;
    }
    #pragma unroll
    for (int k = 0; k < 4; k++) facc[k] += __shfl_xor_sync(0xffffffffu, facc[k], 16);
    ssum = warpSum(ssum);
    float inv = 1.f / (ssum + 1e-16f);

    float4 o = make_float4(-FLT_MAX, -FLT_MAX, -FLT_MAX, -FLT_MAX);
    if (lane < 10) {
        float4 bv = *(const float4*)(b2 + lane * 4);
        o.x = facc[0] * inv + bv.x;
        o.y = facc[1] * inv + bv.y;
        o.z = facc[2] * inv + bv.z;
        o.w = facc[3] * inv + bv.w;
    }
    float mx = fmaxf(fmaxf(o.x, o.y), fmaxf(o.z, o.w));
    mx = warpMax(mx);
    float se = 0.f;
    if (lane < 10)
        se = __expf(o.x - mx) + __expf(o.y - mx) + __expf(o.z - mx) + __expf(o.w - mx);
    se = warpSum(se);
    float lse = __logf(se);
    if (lane < 10) {
        float4 r;
        r.x = o.x - mx - lse; r.y = o.y - mx - lse;
        r.z = o.z - mx - lse; r.w = o.w - mx - lse;
        *(float4*)(dout + (size_t)d * 40 + lane * 4) = r;
    }
}

// ================= launcher =================
extern "C" void kernel_launch(void* const* d_in, const int* in_sizes, int n_in,
                              void* d_out, int out_size) {
    const float* x   = (const float*)d_in[0];
    const int*   ei  = (const int*)  d_in[1];
    const float* W1  = (const float*)d_in[2];
    const float* a1s = (const float*)d_in[3];
    const float* a1d = (const float*)d_in[4];
    const float* b1  = (const float*)d_in[5];
    const float* bng = (const float*)d_in[6];
    const float* bnb = (const float*)d_in[7];
    const float* bnm = (const float*)d_in[8];
    const float* bnv = (const float*)d_in[9];
    const float* W2  = (const float*)d_in[10];
    const float* a2s = (const float*)d_in[11];
    const float* a2d = (const float*)d_in[12];
    const float* b2  = (const float*)d_in[13];
    float* dout = (float*)d_out;

    const int gemm1Smem = (64 + 128) * LDA * (int)sizeof(__half);  // 52224
    cudaFuncSetAttribute(k_gemm1, cudaFuncAttributeMaxDynamicSharedMemorySize, gemm1Smem);

    void* cntPtr = nullptr;
    cudaGetSymbolAddress(&cntPtr, g_cnt);
    cudaMemsetAsync(cntPtr, 0, NN * sizeof(int));

    k_scatter<<<(EE / 4 + 255) / 256, 256>>>(ei);
    k_gemm1  <<<(NN + 63) / 64, 256, gemm1Smem>>>(x, W1, a1s, a1d);
    k_agg1   <<<(NN * 32 + 255) / 256, 256>>>(b1, bng, bnb, bnm, bnv);
    k_gemm2  <<<(NN + 127) / 128, 256>>>(W2, a2s, a2d);
    k_agg2   <<<(NN * 32 + 255) / 256, 256>>>(dout, b2);
}

// round 9
// speedup vs baseline: 1.0617x; 1.0617x over previous
#include <cuda_runtime.h>
#include <cuda_fp16.h>
#include <mma.h>
#include <cfloat>

using namespace nvcuda;

#define NN   50000
#define EE   800000
#define ECAP 64        // ELL capacity for real edges (Poisson(16); P(deg>63) ~ 1e-18)
#define NEG_SLOPE 0.2f
#define BN_EPS 1e-5f
#define LDA 136

// ---------------- scratch (device globals) ----------------
__device__ int g_cnt[NN];
__device__ __align__(16) int g_ell[(size_t)NN * ECAP];
__device__ __align__(16) __half g_h1h [NN * 128];
__device__ float g_al1s[NN * 2];
__device__ float g_al1d[NN * 2];
__device__ __align__(16) __half g_out1h[NN * 128];
__device__ __align__(16) __half g_h2h [NN * 40];
__device__ float g_al2s[NN];
__device__ float g_al2d[NN];

// ---------------- helpers ----------------
__device__ __forceinline__ float lrelu(float x) { return x > 0.f ? x : NEG_SLOPE * x; }
__device__ __forceinline__ float warpSum(float v) {
    #pragma unroll
    for (int o = 16; o; o >>= 1) v += __shfl_xor_sync(0xffffffffu, v, o);
    return v;
}
__device__ __forceinline__ float warpMax(float v) {
    #pragma unroll
    for (int o = 16; o; o >>= 1) v = fmaxf(v, __shfl_xor_sync(0xffffffffu, v, o));
    return v;
}

// ================= K1: init (zero counts; self-loop handled analytically) =================
__global__ void k_init() {
    int i = blockIdx.x * blockDim.x + threadIdx.x;
    if (i < NN) g_cnt[i] = 0;
}

// ================= K2: scatter real edges into ELL =================
__global__ void k_scatter(const int* __restrict__ ei) {
    int t = blockIdx.x * blockDim.x + threadIdx.x;
    if (t >= EE / 4) return;
    int4 s4 = *(const int4*)(ei + t * 4);
    int4 d4 = *(const int4*)(ei + EE + t * 4);
    int p;
    p = atomicAdd(&g_cnt[d4.x], 1); g_ell[(size_t)d4.x * ECAP + p] = s4.x;
    p = atomicAdd(&g_cnt[d4.y], 1); g_ell[(size_t)d4.y * ECAP + p] = s4.y;
    p = atomicAdd(&g_cnt[d4.z], 1); g_ell[(size_t)d4.z * ECAP + p] = s4.z;
    p = atomicAdd(&g_cnt[d4.w], 1); g_ell[(size_t)d4.w * ECAP + p] = s4.w;
}

// ================= K3: GEMM1 wmma fp16, 64-row tiles =================
__global__ __launch_bounds__(256) void k_gemm1(const float* __restrict__ X,
                                               const float* __restrict__ W,
                                               const float* __restrict__ a1s,
                                               const float* __restrict__ a1d) {
    extern __shared__ __align__(16) __half dyn[];
    __half* sA = dyn;                  // 64 x LDA
    __half* sW = dyn + 64 * LDA;       // 128 x LDA
    __shared__ float sAs[128], sAd[128];

    const int tid = threadIdx.x;
    const int warp = tid >> 5, lane = tid & 31;
    const int row0 = blockIdx.x * 64;
    const int validRows = min(64, NN - row0);

    if (tid < 128) { sAs[tid] = a1s[tid]; sAd[tid] = a1d[tid]; }

    #pragma unroll
    for (int i = 0; i < 8; i++) {
        int idx = tid + i * 256;
        int r = idx >> 5, c = (idx & 31) * 4;
        float4 v = make_float4(0.f, 0.f, 0.f, 0.f);
        if (r < validRows) v = *(const float4*)(X + (size_t)(row0 + r) * 128 + c);
        __half2 h0 = __floats2half2_rn(v.x, v.y);
        __half2 h1 = __floats2half2_rn(v.z, v.w);
        uint2 st; st.x = *(unsigned*)&h0; st.y = *(unsigned*)&h1;
        *(uint2*)(sA + r * LDA + c) = st;
    }
    #pragma unroll
    for (int i = 0; i < 16; i++) {
        int idx = tid + i * 256;
        int r = idx >> 5, c = (idx & 31) * 4;
        float4 v = *(const float4*)(W + (size_t)r * 128 + c);
        __half2 h0 = __floats2half2_rn(v.x, v.y);
        __half2 h1 = __floats2half2_rn(v.z, v.w);
        uint2 st; st.x = *(unsigned*)&h0; st.y = *(unsigned*)&h1;
        *(uint2*)(sW + r * LDA + c) = st;
    }
    __syncthreads();

    const int wr = warp & 3;
    const int wc = warp >> 2;

    wmma::fragment<wmma::accumulator, 16, 16, 16, float> acc[4];
    #pragma unroll
    for (int nf = 0; nf < 4; nf++) wmma::fill_fragment(acc[nf], 0.f);
    #pragma unroll
    for (int k0 = 0; k0 < 128; k0 += 16) {
        wmma::fragment<wmma::matrix_a, 16, 16, 16, __half, wmma::row_major> af;
        wmma::load_matrix_sync(af, sA + (wr * 16) * LDA + k0, LDA);
        #pragma unroll
        for (int nf = 0; nf < 4; nf++) {
            wmma::fragment<wmma::matrix_b, 16, 16, 16, __half, wmma::row_major> bf;
            wmma::load_matrix_sync(bf, sW + k0 * LDA + wc * 64 + nf * 16, LDA);
            wmma::mma_sync(acc[nf], af, bf, acc[nf]);
        }
    }
    __syncthreads();

    float* sC = (float*)dyn + warp * 320;
    const int rloc = lane & 15;
    const int coff = (lane >> 4) * 8;
    const int gr = row0 + wr * 16 + rloc;
    float ps = 0.f, pd = 0.f;

    #pragma unroll
    for (int nf = 0; nf < 4; nf++) {
        wmma::store_matrix_sync(sC, acc[nf], 20, wmma::mem_row_major);
        __syncwarp();
        float v[8];
        #pragma unroll
        for (int j = 0; j < 8; j++) v[j] = sC[rloc * 20 + coff + j];
        int cbase = wc * 64 + nf * 16 + coff;
        #pragma unroll
        for (int j = 0; j < 8; j++) { ps += v[j] * sAs[cbase + j]; pd += v[j] * sAd[cbase + j]; }
        if (gr < NN) {
            __half2 h0 = __floats2half2_rn(v[0], v[1]);
            __half2 h1 = __floats2half2_rn(v[2], v[3]);
            __half2 h2 = __floats2half2_rn(v[4], v[5]);
            __half2 h3 = __floats2half2_rn(v[6], v[7]);
            uint4 st;
            st.x = *(unsigned*)&h0; st.y = *(unsigned*)&h1;
            st.z = *(unsigned*)&h2; st.w = *(unsigned*)&h3;
            *(uint4*)(g_h1h + (size_t)gr * 128 + cbase) = st;
        }
        __syncwarp();
    }
    ps += __shfl_xor_sync(0xffffffffu, ps, 16);
    pd += __shfl_xor_sync(0xffffffffu, pd, 16);
    if (lane < 16 && gr < NN) {
        g_al1s[2 * gr + wc] = ps;
        g_al1d[2 * gr + wc] = pd;
    }
}

// ================= K4: layer-1 gather — 16-lane/2-edge, pair loop unrolled x4 (MLP=4) =================
__global__ __launch_bounds__(256) void k_agg1(const float* __restrict__ b1,
                                              const float* __restrict__ gamma,
                                              const float* __restrict__ beta,
                                              const float* __restrict__ mean,
                                              const float* __restrict__ var) {
    int d = (blockIdx.x * blockDim.x + threadIdx.x) >> 5;
    int lane = threadIdx.x & 31;
    if (d >= NN) return;
    const int deg = g_cnt[d];
    const int* row = g_ell + (size_t)d * ECAP;
    float2 ad = *(const float2*)(g_al1d + 2 * d);
    const int half16 = lane >> 4;
    const int l16 = lane & 15;
    const bool head1 = (l16 >= 8);

    // analytic self-loop
    float2 asd = *(const float2*)(g_al1s + 2 * d);
    float e0s = __expf(lrelu(asd.x + ad.x));
    float e1s = __expf(lrelu(asd.y + ad.y));
    float s0 = (lane == 0) ? e0s : 0.f;
    float s1 = (lane == 0) ? e1s : 0.f;

    float facc[8];
    #pragma unroll
    for (int k = 0; k < 8; k++) facc[k] = 0.f;
    if (half16 == 0) {   // self feature contribution once
        float ws = head1 ? e1s : e0s;
        uint4 r = *(const uint4*)(g_h1h + (size_t)d * 128 + l16 * 8);
        float2 f0 = __half22float2(*(__half2*)&r.x);
        float2 f1 = __half22float2(*(__half2*)&r.y);
        float2 f2 = __half22float2(*(__half2*)&r.z);
        float2 f3 = __half22float2(*(__half2*)&r.w);
        facc[0] = f0.x * ws; facc[1] = f0.y * ws;
        facc[2] = f1.x * ws; facc[3] = f1.y * ws;
        facc[4] = f2.x * ws; facc[5] = f2.y * ws;
        facc[6] = f3.x * ws; facc[7] = f3.y * ws;
    }

    for (int base = 0; base < deg; base += 32) {
        int i = base + lane;
        int src = 0; unsigned w01 = 0;    // zero weight for invalid slots
        if (i < deg) {
            src = row[i];
            float2 as = *(const float2*)(g_al1s + 2 * src);
            float e0 = __expf(lrelu(as.x + ad.x));
            float e1 = __expf(lrelu(as.y + ad.y));
            s0 += e0; s1 += e1;
            __half2 p = __floats2half2_rn(e0, e1);
            w01 = *(unsigned*)&p;
        }
        int cnt = min(32, deg - base);
        int pairs = (cnt + 1) >> 1;       // <= 16

        __half2 haccA[4], haccB[4];
        #pragma unroll
        for (int k = 0; k < 4; k++) {
            haccA[k] = __floats2half2_rn(0.f, 0.f);
            haccB[k] = __floats2half2_rn(0.f, 0.f);
        }

        int j = 0;
        for (; j + 4 <= pairs; j += 4) {
            // batch shuffles
            int e0q = 2 * j + half16, e1q = e0q + 2, e2q = e0q + 4, e3q = e0q + 6;
            int      s0q = __shfl_sync(0xffffffffu, src, e0q);
            int      s1q = __shfl_sync(0xffffffffu, src, e1q);
            int      s2q = __shfl_sync(0xffffffffu, src, e2q);
            int      s3q = __shfl_sync(0xffffffffu, src, e3q);
            unsigned w0q = __shfl_sync(0xffffffffu, w01, e0q);
            unsigned w1q = __shfl_sync(0xffffffffu, w01, e1q);
            unsigned w2q = __shfl_sync(0xffffffffu, w01, e2q);
            unsigned w3q = __shfl_sync(0xffffffffu, w01, e3q);
            // batch loads (4 independent LDG.128)
            uint4 r0 = *(const uint4*)(g_h1h + (size_t)s0q * 128 + l16 * 8);
            uint4 r1 = *(const uint4*)(g_h1h + (size_t)s1q * 128 + l16 * 8);
            uint4 r2 = *(const uint4*)(g_h1h + (size_t)s2q * 128 + l16 * 8);
            uint4 r3 = *(const uint4*)(g_h1h + (size_t)s3q * 128 + l16 * 8);
            __half2 h0 = head1 ? __high2half2(*(__half2*)&w0q) : __low2half2(*(__half2*)&w0q);
            __half2 h1 = head1 ? __high2half2(*(__half2*)&w1q) : __low2half2(*(__half2*)&w1q);
            __half2 h2 = head1 ? __high2half2(*(__half2*)&w2q) : __low2half2(*(__half2*)&w2q);
            __half2 h3 = head1 ? __high2half2(*(__half2*)&w3q) : __low2half2(*(__half2*)&w3q);
            haccA[0] = __hfma2(*(__half2*)&r0.x, h0, haccA[0]);
            haccA[1] = __hfma2(*(__half2*)&r0.y, h0, haccA[1]);
            haccA[2] = __hfma2(*(__half2*)&r0.z, h0, haccA[2]);
            haccA[3] = __hfma2(*(__half2*)&r0.w, h0, haccA[3]);
            haccB[0] = __hfma2(*(__half2*)&r1.x, h1, haccB[0]);
            haccB[1] = __hfma2(*(__half2*)&r1.y, h1, haccB[1]);
            haccB[2] = __hfma2(*(__half2*)&r1.z, h1, haccB[2]);
            haccB[3] = __hfma2(*(__half2*)&r1.w, h1, haccB[3]);
            haccA[0] = __hfma2(*(__half2*)&r2.x, h2, haccA[0]);
            haccA[1] = __hfma2(*(__half2*)&r2.y, h2, haccA[1]);
            haccA[2] = __hfma2(*(__half2*)&r2.z, h2, haccA[2]);
            haccA[3] = __hfma2(*(__half2*)&r2.w, h2, haccA[3]);
            haccB[0] = __hfma2(*(__half2*)&r3.x, h3, haccB[0]);
            haccB[1] = __hfma2(*(__half2*)&r3.y, h3, haccB[1]);
            haccB[2] = __hfma2(*(__half2*)&r3.z, h3, haccB[2]);
            haccB[3] = __hfma2(*(__half2*)&r3.w, h3, haccB[3]);
        }
        for (; j < pairs; j++) {
            int esel = 2 * j + half16;
            int      sj = __shfl_sync(0xffffffffu, src, esel);
            unsigned wj = __shfl_sync(0xffffffffu, w01, esel);
            __half2 hw = head1 ? __high2half2(*(__half2*)&wj) : __low2half2(*(__half2*)&wj);
            uint4 r = *(const uint4*)(g_h1h + (size_t)sj * 128 + l16 * 8);
            haccA[0] = __hfma2(*(__half2*)&r.x, hw, haccA[0]);
            haccA[1] = __hfma2(*(__half2*)&r.y, hw, haccA[1]);
            haccA[2] = __hfma2(*(__half2*)&r.z, hw, haccA[2]);
            haccA[3] = __hfma2(*(__half2*)&r.w, hw, haccA[3]);
        }
        // flush chunk to fp32
        #pragma unroll
        for (int k = 0; k < 4; k++) {
            float2 fa = __half22float2(haccA[k]);
            float2 fb = __half22float2(haccB[k]);
            facc[2 * k]     += fa.x + fb.x;
            facc[2 * k + 1] += fa.y + fb.y;
        }
    }
    #pragma unroll
    for (int k = 0; k < 8; k++) facc[k] += __shfl_xor_sync(0xffffffffu, facc[k], 16);
    s0 = warpSum(s0); s1 = warpSum(s1);

    if (lane < 16) {
        float inv = 1.f / ((head1 ? s1 : s0) + 1e-16f);
        int c0 = l16 * 8;
        float o[8];
        #pragma unroll
        for (int h = 0; h < 2; h++) {
            int c = c0 + h * 4;
            float4 bv = *(const float4*)(b1 + c);
            float4 gm = *(const float4*)(gamma + c);
            float4 bt = *(const float4*)(beta + c);
            float4 mn = *(const float4*)(mean + c);
            float4 vr = *(const float4*)(var + c);
            o[h*4+0] = fmaxf((facc[h*4+0] * inv + bv.x - mn.x) * rsqrtf(vr.x + BN_EPS) * gm.x + bt.x, 0.f);
            o[h*4+1] = fmaxf((facc[h*4+1] * inv + bv.y - mn.y) * rsqrtf(vr.y + BN_EPS) * gm.y + bt.y, 0.f);
            o[h*4+2] = fmaxf((facc[h*4+2] * inv + bv.z - mn.z) * rsqrtf(vr.z + BN_EPS) * gm.z + bt.z, 0.f);
            o[h*4+3] = fmaxf((facc[h*4+3] * inv + bv.w - mn.w) * rsqrtf(vr.w + BN_EPS) * gm.w + bt.w, 0.f);
        }
        __half2 p0 = __floats2half2_rn(o[0], o[1]);
        __half2 p1 = __floats2half2_rn(o[2], o[3]);
        __half2 p2 = __floats2half2_rn(o[4], o[5]);
        __half2 p3 = __floats2half2_rn(o[6], o[7]);
        uint4 st;
        st.x = *(unsigned*)&p0; st.y = *(unsigned*)&p1;
        st.z = *(unsigned*)&p2; st.w = *(unsigned*)&p3;
        *(uint4*)(g_out1h + (size_t)d * 128 + c0) = st;
    }
}

// ================= K5: GEMM2 wmma fp16, 64-row tiles, 128 threads =================
__global__ __launch_bounds__(128) void k_gemm2(const float* __restrict__ W2,
                                               const float* __restrict__ a2s,
                                               const float* __restrict__ a2d) {
    __shared__ __align__(16) __half sA[64 * 128];   // 16 KB
    __shared__ __align__(16) __half sB[128 * 48];   // 12 KB
    __shared__ float sAs[48], sAd[48];

    const int tid = threadIdx.x;
    const int warp = tid >> 5, lane = tid & 31;
    const int row0 = blockIdx.x * 64;

    if (tid < 48) {
        sAs[tid] = (tid < 40) ? a2s[tid] : 0.f;
        sAd[tid] = (tid < 40) ? a2d[tid] : 0.f;
    }
    for (int idx = tid; idx < 128 * 48; idx += 128) {
        int r = idx / 48, c = idx % 48;
        sB[idx] = __float2half(c < 40 ? W2[r * 40 + c] : 0.f);
    }
    {
        const int validRows = min(64, NN - row0);
        #pragma unroll
        for (int i = 0; i < 8; i++) {
            int v4 = tid + i * 128;            // 0..1023 uint4 (16 per row)
            int r = v4 >> 4;
            uint4 val = make_uint4(0, 0, 0, 0);
            if (r < validRows)
                val = *(const uint4*)(g_out1h + (size_t)(row0 + r) * 128 + (v4 & 15) * 8);
            *(uint4*)(sA + v4 * 8) = val;
        }
    }
    __syncthreads();

    wmma::fragment<wmma::accumulator, 16, 16, 16, float> acc[3];
    #pragma unroll
    for (int nf = 0; nf < 3; nf++) wmma::fill_fragment(acc[nf], 0.f);
    #pragma unroll
    for (int k0 = 0; k0 < 128; k0 += 16) {
        wmma::fragment<wmma::matrix_a, 16, 16, 16, __half, wmma::row_major> af;
        wmma::load_matrix_sync(af, sA + (warp * 16) * 128 + k0, 128);
        #pragma unroll
        for (int nf = 0; nf < 3; nf++) {
            wmma::fragment<wmma::matrix_b, 16, 16, 16, __half, wmma::row_major> bf;
            wmma::load_matrix_sync(bf, sB + k0 * 48 + nf * 16, 48);
            wmma::mma_sync(acc[nf], af, bf, acc[nf]);
        }
    }
    __syncthreads();

    float* sC = (float*)sA + warp * 320;
    const int rloc = lane & 15;
    const int coff = (lane >> 4) * 8;
    const int gr = row0 + warp * 16 + rloc;
    float ps = 0.f, pd = 0.f;

    #pragma unroll
    for (int nf = 0; nf < 3; nf++) {
        wmma::store_matrix_sync(sC, acc[nf], 20, wmma::mem_row_major);
        __syncwarp();
        float v[8];
        #pragma unroll
        for (int j = 0; j < 8; j++) v[j] = sC[rloc * 20 + coff + j];
        int cbase = nf * 16 + coff;
        #pragma unroll
        for (int j = 0; j < 8; j++) { ps += v[j] * sAs[cbase + j]; pd += v[j] * sAd[cbase + j]; }
        if (gr < NN && cbase < 40) {
            __half2 h0 = __floats2half2_rn(v[0], v[1]);
            __half2 h1 = __floats2half2_rn(v[2], v[3]);
            __half2 h2 = __floats2half2_rn(v[4], v[5]);
            __half2 h3 = __floats2half2_rn(v[6], v[7]);
            uint4 st;
            st.x = *(unsigned*)&h0; st.y = *(unsigned*)&h1;
            st.z = *(unsigned*)&h2; st.w = *(unsigned*)&h3;
            *(uint4*)(g_h2h + (size_t)gr * 40 + cbase) = st;
        }
        __syncwarp();
    }
    ps += __shfl_xor_sync(0xffffffffu, ps, 16);
    pd += __shfl_xor_sync(0xffffffffu, pd, 16);
    if (lane < 16 && gr < NN) { g_al2s[gr] = ps; g_al2d[gr] = pd; }
}

// ================= K6: layer-2 gather, x2 unroll, analytic self-loop, log_softmax =================
__global__ __launch_bounds__(256) void k_agg2(float* __restrict__ dout,
                                              const float* __restrict__ b2) {
    int d = (blockIdx.x * blockDim.x + threadIdx.x) >> 5;
    int lane = threadIdx.x & 31;
    if (d >= NN) return;
    const int deg = g_cnt[d];
    const int* row = g_ell + (size_t)d * ECAP;
    float ad = g_al2d[d];
    const int half16 = lane >> 4;
    const int l16 = lane & 15;

    float evs = __expf(lrelu(g_al2s[d] + ad));
    float ssum = (lane == 0) ? evs : 0.f;
    float facc[4];
    #pragma unroll
    for (int k = 0; k < 4; k++) facc[k] = 0.f;
    if (half16 == 0 && l16 < 10) {
        uint2 r = *(const uint2*)(g_h2h + (size_t)d * 40 + l16 * 4);
        float2 f0 = __half22float2(*(__half2*)&r.x);
        float2 f1 = __half22float2(*(__half2*)&r.y);
        facc[0] = f0.x * evs; facc[1] = f0.y * evs;
        facc[2] = f1.x * evs; facc[3] = f1.y * evs;
    }

    for (int base = 0; base < deg; base += 32) {
        int i = base + lane;
        int src = 0; float ev = 0.f;
        if (i < deg) {
            src = row[i];
            ev = __expf(lrelu(g_al2s[src] + ad));
            ssum += ev;
        }
        int cnt = min(32, deg - base);
        int pairs = (cnt + 1) >> 1;

        __half2 haccA[2], haccB[2];
        haccA[0] = haccA[1] = __floats2half2_rn(0.f, 0.f);
        haccB[0] = haccB[1] = __floats2half2_rn(0.f, 0.f);

        int j = 0;
        for (; j + 2 <= pairs; j += 2) {
            int eselA = 2 * j + half16;
            int eselB = eselA + 2;
            int   sjA = __shfl_sync(0xffffffffu, src, eselA);
            float eA  = __shfl_sync(0xffffffffu, ev, eselA);
            int   sjB = __shfl_sync(0xffffffffu, src, eselB);
            float eB  = __shfl_sync(0xffffffffu, ev, eselB);
            if (l16 < 10) {
                uint2 rA = *(const uint2*)(g_h2h + (size_t)sjA * 40 + l16 * 4);
                uint2 rB = *(const uint2*)(g_h2h + (size_t)sjB * 40 + l16 * 4);
                __half2 hA = __float2half2_rn(eA);
                __half2 hB = __float2half2_rn(eB);
                haccA[0] = __hfma2(*(__half2*)&rA.x, hA, haccA[0]);
                haccA[1] = __hfma2(*(__half2*)&rA.y, hA, haccA[1]);
                haccB[0] = __hfma2(*(__half2*)&rB.x, hB, haccB[0]);
                haccB[1] = __hfma2(*(__half2*)&rB.y, hB, haccB[1]);
            }
        }
        if (j < pairs) {
            int esel = 2 * j + half16;
            int   sj = __shfl_sync(0xffffffffu, src, esel);
            float ej = __shfl_sync(0xffffffffu, ev, esel);
            if (l16 < 10) {
                __half2 hw = __float2half2_rn(ej);
                uint2 r = *(const uint2*)(g_h2h + (size_t)sj * 40 + l16 * 4);
                haccA[0] = __hfma2(*(__half2*)&r.x, hw, haccA[0]);
                haccA[1] = __hfma2(*(__half2*)&r.y, hw, haccA[1]);
            }
        }
        #pragma unroll
        for (int k = 0; k < 2; k++) {
            float2 fa = __half22float2(haccA[k]);
            float2 fb = __half22float2(haccB[k]);
            facc[2 * k]     += fa.x + fb.x;
            facc[2 * k + 1] += fa.y + fb.y;
        }
    }
    #pragma unroll
    for (int k = 0; k < 4; k++) facc[k] += __shfl_xor_sync(0xffffffffu, facc[k], 16);
    ssum = warpSum(ssum);
    float inv = 1.f / (ssum + 1e-16f);

    float4 o = make_float4(-FLT_MAX, -FLT_MAX, -FLT_MAX, -FLT_MAX);
    if (lane < 10) {
        float4 bv = *(const float4*)(b2 + lane * 4);
        o.x = facc[0] * inv + bv.x;
        o.y = facc[1] * inv + bv.y;
        o.z = facc[2] * inv + bv.z;
        o.w = facc[3] * inv + bv.w;
    }
    float mx = fmaxf(fmaxf(o.x, o.y), fmaxf(o.z, o.w));
    mx = warpMax(mx);
    float se = 0.f;
    if (lane < 10)
        se = __expf(o.x - mx) + __expf(o.y - mx) + __expf(o.z - mx) + __expf(o.w - mx);
    se = warpSum(se);
    float lse = __logf(se);
    if (lane < 10) {
        float4 r;
        r.x = o.x - mx - lse; r.y = o.y - mx - lse;
        r.z = o.z - mx - lse; r.w = o.w - mx - lse;
        *(float4*)(dout + (size_t)d * 40 + lane * 4) = r;
    }
}

// ================= launcher =================
extern "C" void kernel_launch(void* const* d_in, const int* in_sizes, int n_in,
                              void* d_out, int out_size) {
    const float* x   = (const float*)d_in[0];
    const int*   ei  = (const int*)  d_in[1];
    const float* W1  = (const float*)d_in[2];
    const float* a1s = (const float*)d_in[3];
    const float* a1d = (const float*)d_in[4];
    const float* b1  = (const float*)d_in[5];
    const float* bng = (const float*)d_in[6];
    const float* bnb = (const float*)d_in[7];
    const float* bnm = (const float*)d_in[8];
    const float* bnv = (const float*)d_in[9];
    const float* W2  = (const float*)d_in[10];
    const float* a2s = (const float*)d_in[11];
    const float* a2d = (const float*)d_in[12];
    const float* b2  = (const float*)d_in[13];
    float* dout = (float*)d_out;

    const int gemm1Smem = (64 + 128) * LDA * (int)sizeof(__half);  // 52224
    cudaFuncSetAttribute(k_gemm1, cudaFuncAttributeMaxDynamicSharedMemorySize, gemm1Smem);

    k_init   <<<(NN + 255) / 256, 256>>>();                              // 1
    k_scatter<<<(EE / 4 + 255) / 256, 256>>>(ei);                        // 2
    k_gemm1  <<<(NN + 63) / 64, 256, gemm1Smem>>>(x, W1, a1s, a1d);      // 3
    k_agg1   <<<(NN * 32 + 255) / 256, 256>>>(b1, bng, bnb, bnm, bnv);   // 4 <- profiled
    k_gemm2  <<<(NN + 63) / 64, 128>>>(W2, a2s, a2d);                    // 5
    k_agg2   <<<(NN * 32 + 255) / 256, 256>>>(dout, b2);                 // 6
}